// round 11
// baseline (speedup 1.0000x reference)
#include <cuda_runtime.h>
#include <cuda_bf16.h>

#define NPTS      8192
#define THREADS   256
#define WPC       8                     // warps per CTA
#define R         8                     // i-points per lane
#define NC        (R / 2)               // packed chains
#define ICHUNK    256                   // i-points per warp task (32*R)
#define IBLKS     (NPTS / ICHUNK)       // 32
#define JTILE     16                    // j-points per warp task
#define JBLKS     (NPTS / JTILE)        // 512
#define JGROUP    16                    // j-blocks per 256-pt j-group
#define RECT_P    (IBLKS / 2)           // 16
#define RECT_C    (IBLKS + 1)           // 33
#define TPT_SYM   (RECT_P * RECT_C * JGROUP)  // 8448
#define TPT_FULL  (IBLKS * JBLKS)             // 16384
#define NTASKS    (2 * TPT_SYM + TPT_FULL)    // 33280: bb, tt, bt(last)
#define GRID      592                   // 4 CTAs/SM * 148 SMs, all resident
#define PREP_CTAS 32
#define LOG2E_F   1.4426950408889634f
#define FULLMASK  0xFFFFFFFFu

typedef unsigned long long ull;

__device__ __forceinline__ float ex2_approx(float x) {
    float r;
    asm("ex2.approx.ftz.f32 %0, %1;" : "=f"(r) : "f"(x));
    return r;
}
__device__ __forceinline__ ull pack2(float lo, float hi) {
    ull p;
    asm("mov.b64 %0, {%1, %2};" : "=l"(p) : "f"(lo), "f"(hi));
    return p;
}
__device__ __forceinline__ unsigned int ld_acq(unsigned int* p) {
    unsigned int v;
    asm volatile("ld.acquire.gpu.u32 %0, [%1];" : "=r"(v) : "l"(p));
    return v;
}
__device__ __forceinline__ void st_rel(unsigned int* p, unsigned int v) {
    asm volatile("st.release.gpu.global.u32 [%0], %1;" :: "l"(p), "r"(v) : "memory");
}

// Scratch (no allocations allowed)
__device__ double g_mean[2];    // sum((bx-tx)*s0), sum((by-ty)*s1)
__device__ float  g_delta[2];   // centroid(base) - centroid(target), scaled
__device__ double g_sum[3];     // Sbb, Stt, Sbt (unnormalized)
__device__ unsigned int g_bar1; // prep reduction completion counter
__device__ unsigned int g_flag; // delta-ready flag
__device__ unsigned int g_task; // dynamic task counter
__device__ unsigned int g_done; // CTA completion counter

__device__ __forceinline__ void block_reduce_add(double v, double* dst,
                                                 double* sred, int tid) {
    sred[tid] = v;
    __syncthreads();
    for (int s = THREADS / 2; s > 0; s >>= 1) {
        if (tid < s) sred[tid] += sred[tid + s];
        __syncthreads();
    }
    if (tid == 0) atomicAdd(dst, sred[0]);
    __syncthreads();
}

// ---------------------------------------------------------------------------
// Warp-autonomous, symmetry-pruned, f32x2-packed pair loop.
//
//  Packed math: two i-points per fma.rn.f32x2 -> FMA-pipe cost 5cyc/pair,
//  MUFU.EX2 8cyc/pair is the sole binding pipe; the slack hides all task
//  overhead. J-tile stores pre-duplicated (u,u)(v,v)(a,a) so the inner loop
//  loads packed operands directly (broadcast LDS, no repacking MOVs).
//
//  bb/tt symmetric at 256x256 block granularity (triangle incl. diagonal,
//  strictly-upper x2) -> effective 2.031*N^2 exps. Triangle remapped to a
//  16x33 rectangle for O(1) decode. Centering folded away; only bt needs
//  delta = cb-ct, reduced by CTAs 0..31 while bb tasks run (bt last).
//  arg = a_i + a_j + x_i*u_j + y_i*v_j = c2*|p_i - p_j|^2,  k = exp2(arg)
// ---------------------------------------------------------------------------
__global__ __launch_bounds__(THREADS, 4) void k_fused(
        const float* __restrict__ base, const float* __restrict__ tgt,
        const float* __restrict__ log_sigma, const float* __restrict__ log_scale,
        float* __restrict__ out) {
    __shared__ ull wtile[WPC][JTILE][4];   // (uu, vv, aa, pad) per j
    __shared__ double sred[THREADS];

    const int tid  = threadIdx.x;
    const int wid  = tid >> 5;
    const int lane = tid & 31;
    const int cta  = blockIdx.x;

    const float s0 = expf(log_scale[0]);
    const float s1 = expf(log_scale[1]);
    const float sigma = expf(log_sigma[0]);
    const float c2 = -(1.0f / (2.0f * sigma * sigma)) * LOG2E_F;
    const float m  = -2.0f * c2;

    const float2* __restrict__ b2 = (const float2*)base;
    const float2* __restrict__ t2 = (const float2*)tgt;

    const unsigned int tbase =
        (unsigned int)__cvta_generic_to_shared(&wtile[wid][0][0]);

    // ---- delta reduction (32 CTAs; bt tasks are last, so this hides) ----
    if (cta < PREP_CTAS) {
        const int i = cta * THREADS + tid;          // 0..8191
        const float2 pb = b2[i];
        const float2 pt = t2[i];
        block_reduce_add((double)(pb.x * s0) - (double)(pt.x * s0),
                         &g_mean[0], sred, tid);
        block_reduce_add((double)(pb.y * s1) - (double)(pt.y * s1),
                         &g_mean[1], sred, tid);
        if (tid == 0) {
            __threadfence();
            unsigned int d = atomicAdd(&g_bar1, 1u);
            if (d == PREP_CTAS - 1) {
                g_delta[0] = (float)(atomicAdd(&g_mean[0], 0.0) / (double)NPTS);
                g_delta[1] = (float)(atomicAdd(&g_mean[1], 0.0) / (double)NPTS);
                st_rel(&g_flag, 1u);
            }
        }
    }

    // ---- warp task loop ----
    double abb = 0.0, att = 0.0, abt = 0.0;
    float dx = 0.0f, dy = 0.0f;
    bool have_delta = false;

    unsigned int tnext = 0u;
    if (lane == 0) tnext = atomicAdd(&g_task, 1u);
    unsigned int t = __shfl_sync(FULLMASK, tnext, 0);

    while (t < NTASKS) {
        // prefetch next task; result consumed only after compute
        if (lane == 0) tnext = atomicAdd(&g_task, 1u);

        // ---- decode task -> (type, it, jt, w) ----
        int type, it, jt;
        float w = 1.0f;
        if (t < 2u * TPT_SYM) {
            type = (t < TPT_SYM) ? 0 : 1;
            unsigned int rem = (t < TPT_SYM) ? t : t - TPT_SYM;
            unsigned int g   = rem >> 4;            // group index [0,528)
            unsigned int sub = rem & 15u;
            unsigned int p = g / RECT_C;            // [0,16)
            unsigned int c = g % RECT_C;            // [0,33)
            unsigned int jg;
            if (c < (unsigned)(IBLKS - p)) { it = (int)p;               jg = p + c; }
            else                           { it = (int)(IBLKS - 1 - p); jg = c - 1; }
            if ((int)jg > it) w = 2.0f;             // strictly-upper block
            jt = (int)(jg * JGROUP + sub);
        } else {
            type = 2;
            unsigned int rem = t - 2u * TPT_SYM;
            it = (int)(rem & (IBLKS - 1));
            jt = (int)(rem >> 5);                   // rem / IBLKS
        }

        // bt gate: one-time per warp; delta long published by now
        if (type == 2 && !have_delta) {
            while (ld_acq(&g_flag) == 0u) { }
            dx = g_delta[0];
            dy = g_delta[1];
            have_delta = true;
        }

        const float2* __restrict__ Araw = (type == 1) ? t2 : b2; // i-side
        const float2* __restrict__ Braw = (type == 0) ? b2 : t2; // j-side
        const float jdx = (type == 2) ? dx : 0.0f;
        const float jdy = (type == 2) ? dy : 0.0f;

        // i-side on the fly, packed into f32x2 chains
        ull xii[NC], yii[NC], aii[NC];
        int i0 = it * ICHUNK + lane;
#pragma unroll
        for (int c = 0; c < NC; c++) {
            float2 p0 = Araw[i0 + (2 * c)     * 32];
            float2 p1 = Araw[i0 + (2 * c + 1) * 32];
            float x0 = p0.x * s0, y0 = p0.y * s1;
            float x1 = p1.x * s0, y1 = p1.y * s1;
            float a0 = c2 * fmaf(x0, x0, y0 * y0);
            float a1 = c2 * fmaf(x1, x1, y1 * y1);
            xii[c] = pack2(x0, x1);
            yii[c] = pack2(y0, y1);
            aii[c] = pack2(a0, a1);
        }

        // warp-private j-tile: pre-duplicated (u,u)(v,v)(a,a)
        __syncwarp();                                // prior tile reads done
        if (lane < JTILE) {
            float2 q = Braw[jt * JTILE + lane];
            float x = fmaf(q.x, s0, jdx);
            float y = fmaf(q.y, s1, jdy);
            float a = c2 * fmaf(x, x, y * y);
            ull uu = pack2(m * x, m * x);
            ull vv = pack2(m * y, m * y);
            ull aa = pack2(a, a);
            unsigned int ta = tbase + lane * 32;
            asm volatile("st.shared.v2.u64 [%0], {%1, %2};"
                         :: "r"(ta), "l"(uu), "l"(vv));
            asm volatile("st.shared.u64 [%0+16], %1;"
                         :: "r"(ta), "l"(aa));
        }
        __syncwarp();

        float acc[R];
#pragma unroll
        for (int r = 0; r < R; r++) acc[r] = 0.0f;

        unsigned int taddr = tbase;
#pragma unroll 4
        for (int j = 0; j < JTILE; j++) {
            ull uu, vv, aa;
            asm("ld.shared.v2.u64 {%0, %1}, [%2];"
                : "=l"(uu), "=l"(vv) : "r"(taddr));
            asm("ld.shared.u64 %0, [%1+16];"
                : "=l"(aa) : "r"(taddr));
            taddr += 32;
#pragma unroll
            for (int c = 0; c < NC; c++) {
                ull arg;
                asm("add.rn.f32x2 %0, %1, %2;"
                    : "=l"(arg) : "l"(aii[c]), "l"(aa));
                asm("fma.rn.f32x2 %0, %1, %2, %3;"
                    : "=l"(arg) : "l"(yii[c]), "l"(vv), "l"(arg));
                asm("fma.rn.f32x2 %0, %1, %2, %3;"
                    : "=l"(arg) : "l"(xii[c]), "l"(uu), "l"(arg));
                float lo, hi;
                asm("mov.b64 {%0, %1}, %2;" : "=f"(lo), "=f"(hi) : "l"(arg));
                acc[2 * c]     += ex2_approx(lo);
                acc[2 * c + 1] += ex2_approx(hi);
            }
        }

        float s = ((acc[0] + acc[1]) + (acc[2] + acc[3])) +
                  ((acc[4] + acc[5]) + (acc[6] + acc[7]));
        double ws = (double)w * (double)s;
        if      (type == 0) abb += ws;
        else if (type == 1) att += ws;
        else                abt += ws;

        t = __shfl_sync(FULLMASK, tnext, 0);
    }

    // ---- CTA-level reduction, then 3 atomics per CTA ----
    __syncthreads();
    block_reduce_add(abb, &g_sum[0], sred, tid);
    block_reduce_add(att, &g_sum[1], sred, tid);
    block_reduce_add(abt, &g_sum[2], sred, tid);

    // ---- finalize + state reset (last CTA) ----
    if (tid == 0) {
        __threadfence();
        unsigned int d = atomicAdd(&g_done, 1u);
        if (d == (unsigned int)(GRID - 1)) {
            double sbb = atomicAdd(&g_sum[0], 0.0);
            double stt = atomicAdd(&g_sum[1], 0.0);
            double sbt = atomicAdd(&g_sum[2], 0.0);
            double inv = 1.0 / ((double)NPTS * (double)NPTS);
            out[0] = (float)((sbb + stt - 2.0 * sbt) * inv);
            // reset for next graph replay
            g_sum[0] = 0.0; g_sum[1] = 0.0; g_sum[2] = 0.0;
            g_mean[0] = 0.0; g_mean[1] = 0.0;
            g_task = 0u; g_bar1 = 0u; g_flag = 0u; g_done = 0u;
            __threadfence();
        }
    }
}

// ---------------------------------------------------------------------------
extern "C" void kernel_launch(void* const* d_in, const int* in_sizes, int n_in,
                              void* d_out, int out_size) {
    const float* base = (const float*)d_in[0];
    const float* tgt  = (const float*)d_in[1];
    const float* lsig = (const float*)d_in[2];
    const float* lsc  = (const float*)d_in[3];

    k_fused<<<GRID, THREADS>>>(base, tgt, lsig, lsc, (float*)d_out);
}

// round 12
// speedup vs baseline: 1.1268x; 1.1268x over previous
#include <cuda_runtime.h>
#include <cuda_bf16.h>

#define NPTS      8192
#define THREADS   256
#define WPC       8                     // warps per CTA
#define R         8                     // i-points per lane
#define NC        (R / 2)               // packed chains
#define ICHUNK    256                   // i-points per warp task (32*R)
#define IBLKS     (NPTS / ICHUNK)       // 32
#define JTILE     32                    // j-points per warp task
#define JBLKS     (NPTS / JTILE)        // 256
#define JGROUP    8                     // j-blocks per 256-pt j-group
#define RECT_P    (IBLKS / 2)           // 16
#define RECT_C    (IBLKS + 1)           // 33
#define TPT_SYM   (RECT_P * RECT_C * JGROUP)  // 4224
#define TPT_FULL  (IBLKS * JBLKS)             // 8192
#define NTASKS    (2 * TPT_SYM + TPT_FULL)    // 16640: bb, tt, bt(last)
#define GRID      592                   // 4 CTAs/SM * 148 SMs, all resident
#define PREP_CTAS 32
#define LOG2E_F   1.4426950408889634f
#define FULLMASK  0xFFFFFFFFu

typedef unsigned long long ull;

__device__ __forceinline__ float ex2_approx(float x) {
    float r;
    asm("ex2.approx.ftz.f32 %0, %1;" : "=f"(r) : "f"(x));
    return r;
}
__device__ __forceinline__ ull pack2(float lo, float hi) {
    ull p;
    asm("mov.b64 %0, {%1, %2};" : "=l"(p) : "f"(lo), "f"(hi));
    return p;
}
__device__ __forceinline__ unsigned int ld_acq(unsigned int* p) {
    unsigned int v;
    asm volatile("ld.acquire.gpu.u32 %0, [%1];" : "=r"(v) : "l"(p));
    return v;
}
__device__ __forceinline__ void st_rel(unsigned int* p, unsigned int v) {
    asm volatile("st.release.gpu.global.u32 [%0], %1;" :: "l"(p), "r"(v) : "memory");
}

// Scratch (no allocations allowed)
__device__ double g_mean[2];    // sum((bx-tx)*s0), sum((by-ty)*s1)
__device__ float  g_delta[2];   // centroid(base) - centroid(target), scaled
__device__ double g_sum[3];     // Sbb, Stt, Sbt (unnormalized)
__device__ unsigned int g_bar1; // prep reduction completion counter
__device__ unsigned int g_flag; // delta-ready flag
__device__ unsigned int g_task; // dynamic task counter
__device__ unsigned int g_done; // CTA completion counter

__device__ __forceinline__ void block_reduce_add(double v, double* dst,
                                                 double* sred, int tid) {
    sred[tid] = v;
    __syncthreads();
    for (int s = THREADS / 2; s > 0; s >>= 1) {
        if (tid < s) sred[tid] += sred[tid + s];
        __syncthreads();
    }
    if (tid == 0) atomicAdd(dst, sred[0]);
    __syncthreads();
}

// ---------------------------------------------------------------------------
// Warp-autonomous, symmetry-pruned, f32x2-packed pair loop.
//
//  Task = 256 i-points x 32 j-points (2048 SMSP-cyc of MUFU) to amortize
//  the per-task serial tax (decode, i-load+pack, tile build, sync, atomic).
//  J-tile is double-buffered per warp: no WAR sync before the write, one
//  syncwarp per task total.
//
//  Packed math: two i-points per fma.rn.f32x2 so the FMA pipe has slack;
//  MUFU.EX2 (8 cyc/pair-of-32) is the sole binding pipe. J-tile stores
//  pre-duplicated (u,u)(v,v)(a,a) so packed operands load directly.
//
//  bb/tt symmetric at 256x256 block granularity (triangle incl. diagonal,
//  strictly-upper x2) -> effective 2.031*N^2 exps. Triangle remapped to a
//  16x33 rectangle for O(1) decode. Centering folded away; only bt needs
//  delta = cb-ct, reduced by CTAs 0..31 while bb tasks run (bt last).
//  arg = a_i + a_j + x_i*u_j + y_i*v_j = c2*|p_i - p_j|^2,  k = exp2(arg)
// ---------------------------------------------------------------------------
__global__ __launch_bounds__(THREADS, 4) void k_fused(
        const float* __restrict__ base, const float* __restrict__ tgt,
        const float* __restrict__ log_sigma, const float* __restrict__ log_scale,
        float* __restrict__ out) {
    __shared__ ull wtile[WPC][2][JTILE][4];   // (uu, vv, aa, pad) per j, x2 buf
    __shared__ double sred[THREADS];

    const int tid  = threadIdx.x;
    const int wid  = tid >> 5;
    const int lane = tid & 31;
    const int cta  = blockIdx.x;

    const float s0 = expf(log_scale[0]);
    const float s1 = expf(log_scale[1]);
    const float sigma = expf(log_sigma[0]);
    const float c2 = -(1.0f / (2.0f * sigma * sigma)) * LOG2E_F;
    const float m  = -2.0f * c2;

    const float2* __restrict__ b2 = (const float2*)base;
    const float2* __restrict__ t2 = (const float2*)tgt;

    const unsigned int tbase =
        (unsigned int)__cvta_generic_to_shared(&wtile[wid][0][0][0]);

    // ---- delta reduction (32 CTAs; bt tasks are last, so this hides) ----
    if (cta < PREP_CTAS) {
        const int i = cta * THREADS + tid;          // 0..8191
        const float2 pb = b2[i];
        const float2 pt = t2[i];
        block_reduce_add((double)(pb.x * s0) - (double)(pt.x * s0),
                         &g_mean[0], sred, tid);
        block_reduce_add((double)(pb.y * s1) - (double)(pt.y * s1),
                         &g_mean[1], sred, tid);
        if (tid == 0) {
            __threadfence();
            unsigned int d = atomicAdd(&g_bar1, 1u);
            if (d == PREP_CTAS - 1) {
                g_delta[0] = (float)(atomicAdd(&g_mean[0], 0.0) / (double)NPTS);
                g_delta[1] = (float)(atomicAdd(&g_mean[1], 0.0) / (double)NPTS);
                st_rel(&g_flag, 1u);
            }
        }
    }

    // ---- warp task loop ----
    double abb = 0.0, att = 0.0, abt = 0.0;
    float dx = 0.0f, dy = 0.0f;
    bool have_delta = false;
    unsigned int buf = 0u;

    unsigned int tnext = 0u;
    if (lane == 0) tnext = atomicAdd(&g_task, 1u);
    unsigned int t = __shfl_sync(FULLMASK, tnext, 0);

    while (t < NTASKS) {
        // prefetch next task; result consumed only after compute
        if (lane == 0) tnext = atomicAdd(&g_task, 1u);

        // ---- decode task -> (type, it, jt, w) ----
        int type, it, jt;
        float w = 1.0f;
        if (t < 2u * TPT_SYM) {
            type = (t < TPT_SYM) ? 0 : 1;
            unsigned int rem = (t < TPT_SYM) ? t : t - TPT_SYM;
            unsigned int g   = rem >> 3;            // group index [0,528)
            unsigned int sub = rem & 7u;
            unsigned int p = g / RECT_C;            // [0,16)
            unsigned int c = g % RECT_C;            // [0,33)
            unsigned int jg;
            if (c < (unsigned)(IBLKS - p)) { it = (int)p;               jg = p + c; }
            else                           { it = (int)(IBLKS - 1 - p); jg = c - 1; }
            if ((int)jg > it) w = 2.0f;             // strictly-upper block
            jt = (int)(jg * JGROUP + sub);
        } else {
            type = 2;
            unsigned int rem = t - 2u * TPT_SYM;
            it = (int)(rem & (IBLKS - 1));
            jt = (int)(rem >> 5);                   // rem / IBLKS
        }

        // bt gate: one-time per warp; delta long published by now
        if (type == 2 && !have_delta) {
            while (ld_acq(&g_flag) == 0u) { }
            dx = g_delta[0];
            dy = g_delta[1];
            have_delta = true;
        }

        const float2* __restrict__ Araw = (type == 1) ? t2 : b2; // i-side
        const float2* __restrict__ Braw = (type == 0) ? b2 : t2; // j-side
        const float jdx = (type == 2) ? dx : 0.0f;
        const float jdy = (type == 2) ? dy : 0.0f;

        // warp-private j-tile, double-buffered: pre-duplicated (u,u)(v,v)(a,a)
        {
            float2 q = Braw[jt * JTILE + lane];
            float x = fmaf(q.x, s0, jdx);
            float y = fmaf(q.y, s1, jdy);
            float a = c2 * fmaf(x, x, y * y);
            ull uu = pack2(m * x, m * x);
            ull vv = pack2(m * y, m * y);
            ull aa = pack2(a, a);
            unsigned int ta = tbase + buf * (JTILE * 32) + lane * 32;
            asm volatile("st.shared.v2.u64 [%0], {%1, %2};"
                         :: "r"(ta), "l"(uu), "l"(vv));
            asm volatile("st.shared.u64 [%0+16], %1;"
                         :: "r"(ta), "l"(aa));
        }

        // i-side on the fly, packed into f32x2 chains
        ull xii[NC], yii[NC], aii[NC];
        int i0 = it * ICHUNK + lane;
#pragma unroll
        for (int c = 0; c < NC; c++) {
            float2 p0 = Araw[i0 + (2 * c)     * 32];
            float2 p1 = Araw[i0 + (2 * c + 1) * 32];
            float x0 = p0.x * s0, y0 = p0.y * s1;
            float x1 = p1.x * s0, y1 = p1.y * s1;
            float a0 = c2 * fmaf(x0, x0, y0 * y0);
            float a1 = c2 * fmaf(x1, x1, y1 * y1);
            xii[c] = pack2(x0, x1);
            yii[c] = pack2(y0, y1);
            aii[c] = pack2(a0, a1);
        }

        __syncwarp();                   // tile writes visible to all lanes

        float acc[R];
#pragma unroll
        for (int r = 0; r < R; r++) acc[r] = 0.0f;

        unsigned int taddr = tbase + buf * (JTILE * 32);
#pragma unroll 4
        for (int j = 0; j < JTILE; j++) {
            ull uu, vv, aa;
            asm("ld.shared.v2.u64 {%0, %1}, [%2];"
                : "=l"(uu), "=l"(vv) : "r"(taddr));
            asm("ld.shared.u64 %0, [%1+16];"
                : "=l"(aa) : "r"(taddr));
            taddr += 32;
#pragma unroll
            for (int c = 0; c < NC; c++) {
                ull arg;
                asm("add.rn.f32x2 %0, %1, %2;"
                    : "=l"(arg) : "l"(aii[c]), "l"(aa));
                asm("fma.rn.f32x2 %0, %1, %2, %3;"
                    : "=l"(arg) : "l"(yii[c]), "l"(vv), "l"(arg));
                asm("fma.rn.f32x2 %0, %1, %2, %3;"
                    : "=l"(arg) : "l"(xii[c]), "l"(uu), "l"(arg));
                float lo, hi;
                asm("mov.b64 {%0, %1}, %2;" : "=f"(lo), "=f"(hi) : "l"(arg));
                acc[2 * c]     += ex2_approx(lo);
                acc[2 * c + 1] += ex2_approx(hi);
            }
        }

        float s = ((acc[0] + acc[1]) + (acc[2] + acc[3])) +
                  ((acc[4] + acc[5]) + (acc[6] + acc[7]));
        double ws = (double)w * (double)s;
        if      (type == 0) abb += ws;
        else if (type == 1) att += ws;
        else                abt += ws;

        buf ^= 1u;
        t = __shfl_sync(FULLMASK, tnext, 0);
    }

    // ---- CTA-level reduction, then 3 atomics per CTA ----
    __syncthreads();
    block_reduce_add(abb, &g_sum[0], sred, tid);
    block_reduce_add(att, &g_sum[1], sred, tid);
    block_reduce_add(abt, &g_sum[2], sred, tid);

    // ---- finalize + state reset (last CTA) ----
    if (tid == 0) {
        __threadfence();
        unsigned int d = atomicAdd(&g_done, 1u);
        if (d == (unsigned int)(GRID - 1)) {
            double sbb = atomicAdd(&g_sum[0], 0.0);
            double stt = atomicAdd(&g_sum[1], 0.0);
            double sbt = atomicAdd(&g_sum[2], 0.0);
            double inv = 1.0 / ((double)NPTS * (double)NPTS);
            out[0] = (float)((sbb + stt - 2.0 * sbt) * inv);
            // reset for next graph replay
            g_sum[0] = 0.0; g_sum[1] = 0.0; g_sum[2] = 0.0;
            g_mean[0] = 0.0; g_mean[1] = 0.0;
            g_task = 0u; g_bar1 = 0u; g_flag = 0u; g_done = 0u;
            __threadfence();
        }
    }
}

// ---------------------------------------------------------------------------
extern "C" void kernel_launch(void* const* d_in, const int* in_sizes, int n_in,
                              void* d_out, int out_size) {
    const float* base = (const float*)d_in[0];
    const float* tgt  = (const float*)d_in[1];
    const float* lsig = (const float*)d_in[2];
    const float* lsc  = (const float*)d_in[3];

    k_fused<<<GRID, THREADS>>>(base, tgt, lsig, lsc, (float*)d_out);
}